// round 6
// baseline (speedup 1.0000x reference)
#include <cuda_runtime.h>

#define RB 131072
#define RT 6
#define RV 31
#define RL 3
#define WST 32           // padded j-stride in shared weight arrays

// Inter-layer activation scratch: [B][T][V], ~93 MiB (mostly L2-resident).
__device__ float g_scratch[(size_t)RB * RT * RV];

// tanh(x) = 1 - 2/(exp(2x)+1); MUFU-based, rel err ~1e-6, saturates at +/-1.
__device__ __forceinline__ float tanh_fast(float x) {
    float e = __expf(2.0f * x);
    return 1.0f - __fdividef(2.0f, e + 1.0f);
}

// Shared weights: w2[k*WST + j] = {Wih[j,k], Whh[j,k]}  (broadcast LDS.64)
//                 bsum[j] = bih[j] + bhh[j]
__device__ __forceinline__ void fill_w(float2* w2, float* bsum,
                                       const float* __restrict__ Wih,
                                       const float* __restrict__ Whh,
                                       const float* __restrict__ bih,
                                       const float* __restrict__ bhh,
                                       int tid)
{
    for (int i = tid; i < RV * RV; i += 128) {
        int k = i / RV, j = i - k * RV;
        w2[k * WST + j] = make_float2(Wih[j * RV + k], Whh[j * RV + k]);
    }
    if (tid < RV) bsum[tid] = bih[tid] + bhh[tid];
}

// One RNN layer over all T steps; one batch element per thread.
__global__ void __launch_bounds__(128, 8)
rnn_layer(const float* xin_ext, int use_ext_in,
          const float* __restrict__ h0,
          const float* __restrict__ Wih, const float* __restrict__ Whh,
          const float* __restrict__ bih, const float* __restrict__ bhh)
{
    __shared__ float2 w2[RV * WST];
    __shared__ float bsum[RV];
    const int tid = threadIdx.x;
    fill_w(w2, bsum, Wih, Whh, bih, bhh, tid);
    __syncthreads();

    const size_t b = (size_t)blockIdx.x * 128 + tid;
    const float* xin = use_ext_in ? xin_ext : g_scratch;
    const float* xr = xin + b * (RT * RV);
    float* orow = g_scratch + b * (RT * RV);

    float h[RV];
#pragma unroll
    for (int j = 0; j < RV; ++j) h[j] = h0[b * RV + j];

#pragma unroll 1
    for (int t = 0; t < RT; ++t) {
        float acc[RV];
#pragma unroll
        for (int j = 0; j < RV; ++j) acc[j] = bsum[j];

#pragma unroll
        for (int k = 0; k < RV; ++k) {
            const float xk = xr[t * RV + k];
            const float hk = h[k];
            const float2* wr = w2 + k * WST;
#pragma unroll
            for (int j = 0; j < RV; ++j) {
                float2 w = wr[j];                 // LDS.64 broadcast
                acc[j] = fmaf(w.x, xk, acc[j]);
                acc[j] = fmaf(w.y, hk, acc[j]);
            }
        }
#pragma unroll
        for (int j = 0; j < RV; ++j) {
            float v = tanh_fast(acc[j]);
            h[j] = v;
            orow[t * RV + j] = v;
        }
    }
}

// Layer 2 recurrence (no intermediate stores) + linear + tanh + softmax.
__global__ void __launch_bounds__(128, 8)
rnn_final(const float* __restrict__ h0,
          const float* __restrict__ Wih, const float* __restrict__ Whh,
          const float* __restrict__ bih, const float* __restrict__ bhh,
          const float* __restrict__ Wlin, const float* __restrict__ blin,
          float* __restrict__ out)
{
    __shared__ float2 w2[RV * WST];
    __shared__ float bsum[RV];
    __shared__ float wl[RV * WST];   // wl[k*WST + j] = Wlin[j,k]
    __shared__ float bl[RV];

    const int tid = threadIdx.x;
    fill_w(w2, bsum, Wih, Whh, bih, bhh, tid);
    for (int i = tid; i < RV * RV; i += 128) {
        int k = i / RV, j = i - k * RV;
        wl[k * WST + j] = Wlin[j * RV + k];
    }
    if (tid < RV) bl[tid] = blin[tid];
    __syncthreads();

    const size_t b = (size_t)blockIdx.x * 128 + tid;
    const float* xr = g_scratch + b * (RT * RV);

    float h[RV];
#pragma unroll
    for (int j = 0; j < RV; ++j) h[j] = h0[b * RV + j];

#pragma unroll 1
    for (int t = 0; t < RT; ++t) {
        float acc[RV];
#pragma unroll
        for (int j = 0; j < RV; ++j) acc[j] = bsum[j];

#pragma unroll
        for (int k = 0; k < RV; ++k) {
            const float xk = xr[t * RV + k];
            const float hk = h[k];
            const float2* wr = w2 + k * WST;
#pragma unroll
            for (int j = 0; j < RV; ++j) {
                float2 w = wr[j];
                acc[j] = fmaf(w.x, xk, acc[j]);
                acc[j] = fmaf(w.y, hk, acc[j]);
            }
        }
#pragma unroll
        for (int j = 0; j < RV; ++j) h[j] = tanh_fast(acc[j]);
    }

    // linear + tanh on final h
    float y[RV];
#pragma unroll
    for (int j = 0; j < RV; ++j) y[j] = bl[j];
#pragma unroll
    for (int k = 0; k < RV; ++k) {
        const float hk = h[k];
        const float* wr = wl + k * WST;
#pragma unroll
        for (int j = 0; j < RV; ++j)
            y[j] = fmaf(wr[j], hk, y[j]);
    }
#pragma unroll
    for (int j = 0; j < RV; ++j) y[j] = tanh_fast(y[j]);

    // softmax over V
    float m = y[0];
#pragma unroll
    for (int j = 1; j < RV; ++j) m = fmaxf(m, y[j]);
    float s = 0.0f;
#pragma unroll
    for (int j = 0; j < RV; ++j) { y[j] = __expf(y[j] - m); s += y[j]; }
    const float inv = __fdividef(1.0f, s);
#pragma unroll
    for (int j = 0; j < RV; ++j) out[b * RV + j] = y[j] * inv;
}

extern "C" void kernel_launch(void* const* d_in, const int* in_sizes, int n_in,
                              void* d_out, int out_size)
{
    const float* inp  = (const float*)d_in[0];  // [B,T,V]
    const float* h0   = (const float*)d_in[1];  // [L,B,V]
    const float* Wih  = (const float*)d_in[2];  // [L,V,V]
    const float* Whh  = (const float*)d_in[3];  // [L,V,V]
    const float* bih  = (const float*)d_in[4];  // [L,V]
    const float* bhh  = (const float*)d_in[5];  // [L,V]
    const float* Wlin = (const float*)d_in[6];  // [V,V]
    const float* blin = (const float*)d_in[7];  // [V]
    float* out = (float*)d_out;                 // [B,V]

    (void)in_sizes; (void)n_in; (void)out_size;

    const dim3 grid(RB / 128), block(128);

    // layer 0: inp -> scratch
    rnn_layer<<<grid, block>>>(inp, 1, h0, Wih, Whh, bih, bhh);
    // layer 1: scratch -> scratch (in-place, each thread owns its row)
    rnn_layer<<<grid, block>>>(nullptr, 0, h0 + (size_t)RB * RV,
                               Wih + RV * RV, Whh + RV * RV,
                               bih + RV, bhh + RV);
    // layer 2 + linear + tanh + softmax
    rnn_final<<<grid, block>>>(h0 + 2 * (size_t)RB * RV,
                               Wih + 2 * RV * RV, Whh + 2 * RV * RV,
                               bih + 2 * RV, bhh + 2 * RV,
                               Wlin, blin, out);
}

// round 7
// speedup vs baseline: 1.1110x; 1.1110x over previous
#include <cuda_runtime.h>

#define RB 131072
#define RT 6
#define RV 31
#define RL 3
#define WST 32           // padded j-stride in shared weight arrays

// Inter-layer activation scratch: [B][T][V], ~93 MiB (mostly L2-resident).
__device__ float g_scratch[(size_t)RB * RT * RV];

// tanh(x) = 1 - 2/(exp(2x)+1); MUFU-based, rel err ~1e-6, saturates at +/-1.
__device__ __forceinline__ float tanh_fast(float x) {
    float e = __expf(2.0f * x);
    return 1.0f - __fdividef(2.0f, e + 1.0f);
}

// Shared weights: w2[k*WST + j] = {Wih[j,k], Whh[j,k]}  (broadcast LDS.64)
//                 bsum[j] = bih[j] + bhh[j]
__device__ __forceinline__ void fill_w(float2* w2, float* bsum,
                                       const float* __restrict__ Wih,
                                       const float* __restrict__ Whh,
                                       const float* __restrict__ bih,
                                       const float* __restrict__ bhh,
                                       int tid)
{
    for (int i = tid; i < RV * RV; i += 128) {
        int k = i / RV, j = i - k * RV;
        w2[k * WST + j] = make_float2(Wih[j * RV + k], Whh[j * RV + k]);
    }
    if (tid < RV) bsum[tid] = bih[tid] + bhh[tid];
}

// One RNN layer over all T steps; one batch element per thread.
// min-blocks=4 -> 128-reg budget: h[31]+acc[31] stay in registers (no spill).
__global__ void __launch_bounds__(128, 4)
rnn_layer(const float* xin_ext, int use_ext_in,
          const float* __restrict__ h0,
          const float* __restrict__ Wih, const float* __restrict__ Whh,
          const float* __restrict__ bih, const float* __restrict__ bhh)
{
    __shared__ float2 w2[RV * WST];
    __shared__ float bsum[RV];
    const int tid = threadIdx.x;
    fill_w(w2, bsum, Wih, Whh, bih, bhh, tid);
    __syncthreads();

    const size_t b = (size_t)blockIdx.x * 128 + tid;
    const float* xin = use_ext_in ? xin_ext : g_scratch;
    const float* xr = xin + b * (RT * RV);
    float* orow = g_scratch + b * (RT * RV);

    float h[RV];
#pragma unroll
    for (int j = 0; j < RV; ++j) h[j] = h0[b * RV + j];

#pragma unroll 1
    for (int t = 0; t < RT; ++t) {
        float acc[RV];
#pragma unroll
        for (int j = 0; j < RV; ++j) acc[j] = bsum[j];

#pragma unroll
        for (int k = 0; k < RV; ++k) {
            const float xk = xr[t * RV + k];
            const float hk = h[k];
            const float2* wr = w2 + k * WST;
#pragma unroll
            for (int j = 0; j < RV; ++j) {
                float2 w = wr[j];                 // LDS.64 broadcast
                acc[j] = fmaf(w.x, xk, acc[j]);
                acc[j] = fmaf(w.y, hk, acc[j]);
            }
        }
#pragma unroll
        for (int j = 0; j < RV; ++j) {
            float v = tanh_fast(acc[j]);
            h[j] = v;
            orow[t * RV + j] = v;
        }
    }
}

// Layer 2 recurrence (no intermediate stores) + linear + tanh + softmax.
__global__ void __launch_bounds__(128, 4)
rnn_final(const float* __restrict__ h0,
          const float* __restrict__ Wih, const float* __restrict__ Whh,
          const float* __restrict__ bih, const float* __restrict__ bhh,
          const float* __restrict__ Wlin, const float* __restrict__ blin,
          float* __restrict__ out)
{
    __shared__ float2 w2[RV * WST];
    __shared__ float bsum[RV];
    __shared__ float wl[RV * WST];   // wl[k*WST + j] = Wlin[j,k]
    __shared__ float bl[RV];

    const int tid = threadIdx.x;
    fill_w(w2, bsum, Wih, Whh, bih, bhh, tid);
    for (int i = tid; i < RV * RV; i += 128) {
        int k = i / RV, j = i - k * RV;
        wl[k * WST + j] = Wlin[j * RV + k];
    }
    if (tid < RV) bl[tid] = blin[tid];
    __syncthreads();

    const size_t b = (size_t)blockIdx.x * 128 + tid;
    const float* xr = g_scratch + b * (RT * RV);

    float h[RV];
#pragma unroll
    for (int j = 0; j < RV; ++j) h[j] = h0[b * RV + j];

#pragma unroll 1
    for (int t = 0; t < RT; ++t) {
        float acc[RV];
#pragma unroll
        for (int j = 0; j < RV; ++j) acc[j] = bsum[j];

#pragma unroll
        for (int k = 0; k < RV; ++k) {
            const float xk = xr[t * RV + k];
            const float hk = h[k];
            const float2* wr = w2 + k * WST;
#pragma unroll
            for (int j = 0; j < RV; ++j) {
                float2 w = wr[j];
                acc[j] = fmaf(w.x, xk, acc[j]);
                acc[j] = fmaf(w.y, hk, acc[j]);
            }
        }
#pragma unroll
        for (int j = 0; j < RV; ++j) h[j] = tanh_fast(acc[j]);
    }

    // linear + tanh on final h
    float y[RV];
#pragma unroll
    for (int j = 0; j < RV; ++j) y[j] = bl[j];
#pragma unroll
    for (int k = 0; k < RV; ++k) {
        const float hk = h[k];
        const float* wr = wl + k * WST;
#pragma unroll
        for (int j = 0; j < RV; ++j)
            y[j] = fmaf(wr[j], hk, y[j]);
    }
#pragma unroll
    for (int j = 0; j < RV; ++j) y[j] = tanh_fast(y[j]);

    // softmax over V
    float m = y[0];
#pragma unroll
    for (int j = 1; j < RV; ++j) m = fmaxf(m, y[j]);
    float s = 0.0f;
#pragma unroll
    for (int j = 0; j < RV; ++j) { y[j] = __expf(y[j] - m); s += y[j]; }
    const float inv = __fdividef(1.0f, s);
#pragma unroll
    for (int j = 0; j < RV; ++j) out[b * RV + j] = y[j] * inv;
}

extern "C" void kernel_launch(void* const* d_in, const int* in_sizes, int n_in,
                              void* d_out, int out_size)
{
    const float* inp  = (const float*)d_in[0];  // [B,T,V]
    const float* h0   = (const float*)d_in[1];  // [L,B,V]
    const float* Wih  = (const float*)d_in[2];  // [L,V,V]
    const float* Whh  = (const float*)d_in[3];  // [L,V,V]
    const float* bih  = (const float*)d_in[4];  // [L,V]
    const float* bhh  = (const float*)d_in[5];  // [L,V]
    const float* Wlin = (const float*)d_in[6];  // [V,V]
    const float* blin = (const float*)d_in[7];  // [V]
    float* out = (float*)d_out;                 // [B,V]

    (void)in_sizes; (void)n_in; (void)out_size;

    const dim3 grid(RB / 128), block(128);

    // layer 0: inp -> scratch
    rnn_layer<<<grid, block>>>(inp, 1, h0, Wih, Whh, bih, bhh);
    // layer 1: scratch -> scratch (in-place, each thread owns its row)
    rnn_layer<<<grid, block>>>(nullptr, 0, h0 + (size_t)RB * RV,
                               Wih + RV * RV, Whh + RV * RV,
                               bih + RV, bhh + RV);
    // layer 2 + linear + tanh + softmax
    rnn_final<<<grid, block>>>(h0 + 2 * (size_t)RB * RV,
                               Wih + 2 * RV * RV, Whh + 2 * RV * RV,
                               bih + 2 * RV, bhh + 2 * RV,
                               Wlin, blin, out);
}